// round 15
// baseline (speedup 1.0000x reference)
#include <cuda_runtime.h>
#include <cuda_fp16.h>
#include <math.h>
#include <stdint.h>

// Problem constants
#define BATCH 8
#define SEQ_T 1024
#define SEQ_TP 64
#define CH 1024
#define NHEAD 16
#define HDIM 64
#define C3 (3 * CH)

// Scratch (device globals: allocation-free rule)
__device__ __half g_x16[BATCH * SEQ_T * CH];
__device__ __half g_prefix16[BATCH * SEQ_TP * CH];
__device__ __half g_wattn16[CH * C3];
__device__ __half g_wprefix16[CH * C3];
__device__ __half g_wproj16[CH * CH];
__device__ __half g_qkv16[BATCH * SEQ_T * C3];
__device__ __half g_pqkv16[BATCH * SEQ_TP * C3];
__device__ __half g_y16[BATCH * SEQ_T * CH];

// ===========================================================================
// helpers (compute_80+ features only)
// ===========================================================================
__device__ __forceinline__ void mma_f16(float* d, const uint32_t* a, const uint32_t* b) {
    asm volatile(
        "mma.sync.aligned.m16n8k16.row.col.f32.f16.f16.f32 "
        "{%0,%1,%2,%3}, {%4,%5,%6,%7}, {%8,%9}, {%0,%1,%2,%3};"
        : "+f"(d[0]), "+f"(d[1]), "+f"(d[2]), "+f"(d[3])
        : "r"(a[0]), "r"(a[1]), "r"(a[2]), "r"(a[3]), "r"(b[0]), "r"(b[1]));
}

__device__ __forceinline__ void ldsm_x4(uint32_t* r, uint32_t addr) {
    asm volatile(
        "ldmatrix.sync.aligned.m8n8.x4.shared.b16 {%0,%1,%2,%3}, [%4];"
        : "=r"(r[0]), "=r"(r[1]), "=r"(r[2]), "=r"(r[3]) : "r"(addr));
}

__device__ __forceinline__ void ldsm_x4_t(uint32_t* r, uint32_t addr) {
    asm volatile(
        "ldmatrix.sync.aligned.m8n8.x4.trans.shared.b16 {%0,%1,%2,%3}, [%4];"
        : "=r"(r[0]), "=r"(r[1]), "=r"(r[2]), "=r"(r[3]) : "r"(addr));
}

// pack {hi, lo} -> f16x2 (lo in lower half)
__device__ __forceinline__ uint32_t pack_f16(float hi, float lo) {
    uint32_t h;
    asm("cvt.rn.f16x2.f32 %0, %1, %2;" : "=r"(h) : "f"(hi), "f"(lo));
    return h;
}

__device__ __forceinline__ float ex2f(float x) {
    float r;
    asm("ex2.approx.ftz.f32 %0, %1;" : "=f"(r) : "f"(x));
    return r;
}

// ex2 on packed f16x2 (one MUFU op for two values)
__device__ __forceinline__ uint32_t h2ex2(uint32_t x) {
    uint32_t r;
    asm("ex2.approx.f16x2 %0, %1;" : "=r"(r) : "r"(x));
    return r;
}

__device__ __forceinline__ uint32_t smem_u32(const void* p) {
    uint32_t a;
    asm("{ .reg .u64 t; cvta.to.shared.u64 t, %1; cvt.u32.u64 %0, t; }"
        : "=r"(a) : "l"(p));
    return a;
}

__device__ __forceinline__ void cp16(uint32_t dst, const void* src) {
    asm volatile("cp.async.cg.shared.global [%0], [%1], 16;" :: "r"(dst), "l"(src));
}
#define CP_COMMIT() asm volatile("cp.async.commit_group;" ::: "memory")
#define CP_WAIT(n)  asm volatile("cp.async.wait_group %0;" :: "n"(n) : "memory")

// ===========================================================================
// Fused fp32 -> fp16 conversion over all 5 tensors (one launch).
// ===========================================================================
#define CVT_N_X   (BATCH * SEQ_T * CH / 4)
#define CVT_N_P   (BATCH * SEQ_TP * CH / 4)
#define CVT_N_WA  (CH * C3 / 4)
#define CVT_N_WP  (CH * C3 / 4)
#define CVT_N_WO  (CH * CH / 4)
#define CVT_E1 (CVT_N_X)
#define CVT_E2 (CVT_E1 + CVT_N_P)
#define CVT_E3 (CVT_E2 + CVT_N_WA)
#define CVT_E4 (CVT_E3 + CVT_N_WP)
#define CVT_TOT (CVT_E4 + CVT_N_WO)

__global__ void cvt_all_f16(const float* __restrict__ x, const float* __restrict__ p,
                            const float* __restrict__ wa, const float* __restrict__ wp,
                            const float* __restrict__ wo,
                            uint32_t* __restrict__ ox, uint32_t* __restrict__ op,
                            uint32_t* __restrict__ owa, uint32_t* __restrict__ owp,
                            uint32_t* __restrict__ owo) {
    int i = blockIdx.x * blockDim.x + threadIdx.x;
    if (i >= CVT_TOT) return;
    const float* src;
    uint32_t* dst;
    int j;
    if (i < CVT_E1)      { src = x;  dst = ox;  j = i; }
    else if (i < CVT_E2) { src = p;  dst = op;  j = i - CVT_E1; }
    else if (i < CVT_E3) { src = wa; dst = owa; j = i - CVT_E2; }
    else if (i < CVT_E4) { src = wp; dst = owp; j = i - CVT_E3; }
    else                 { src = wo; dst = owo; j = i - CVT_E4; }
    float4 v = ((const float4*)src)[j];
    uint2 o;
    o.x = pack_f16(v.y, v.x);
    o.y = pack_f16(v.w, v.z);
    *(uint2*)&dst[2 * j] = o;
}

// ===========================================================================
// fp16 tensor-core GEMM body, compile-time dims: C = A[.,K] @ B[K,N] + bias.
// Block 128x128, BK=32, 128 thr (4 warps 2x2, warp tile 64x64).
// 4-stage cp.async ring, WAIT(2), single barrier per chunk.
// ===========================================================================
#define A_STG 10240
#define B_STG 8704
#define NSTG 4
#define B_OFF (NSTG * A_STG)
#define GEMM_SMEM (B_OFF + NSTG * B_STG)   // 75776 bytes

template <bool OUT_HALF, int N, int K>
__device__ __forceinline__
void gemm_body(const __half* __restrict__ A,
               const __half* __restrict__ B,
               const float* __restrict__ bias,
               float* __restrict__ Cf,
               __half* __restrict__ Ch,
               int row0, int col0, uint32_t sm_b) {
    const int tid = threadIdx.x;
    const int wid = tid >> 5;
    const int lane = tid & 31;
    const int r = lane >> 2;
    const int c = lane & 3;
    const int wm = (wid >> 1) * 64;
    const int wn = (wid & 1) * 64;

    const int mat = lane >> 3;
    const int m8r = lane & 7;
    const int a_mloc = (mat & 1) * 8 + m8r;
    const int a_koffB = (mat >> 1) * 16;
    const int b_kloc = (mat & 1) * 8 + m8r;
    const int b_nloc = (mat >> 1) * 8;

    float acc[4][8][4];
#pragma unroll
    for (int mt = 0; mt < 4; mt++)
#pragma unroll
        for (int nt = 0; nt < 8; nt++)
#pragma unroll
            for (int j = 0; j < 4; j++) acc[mt][nt][j] = 0.0f;

    constexpr int nch = K >> 5;

    auto load_stage = [&](int ch, int st) {
#pragma unroll
        for (int i = 0; i < 4; i++) {
            int idx = tid + i * 128;
            int rw = idx >> 2;
            int ck = idx & 3;
            uint32_t dst = sm_b + (uint32_t)(st * A_STG + rw * 80 + ck * 16);
            cp16(dst, A + (size_t)(row0 + rw) * K + ch * 32 + ck * 8);
        }
#pragma unroll
        for (int i = 0; i < 4; i++) {
            int idx = tid + i * 128;
            int kk = idx >> 4;
            int ck = idx & 15;
            uint32_t dst = sm_b + (uint32_t)(B_OFF + st * B_STG + kk * 272 + ck * 16);
            cp16(dst, B + (size_t)(ch * 32 + kk) * N + col0 + ck * 8);
        }
        CP_COMMIT();
    };

    load_stage(0, 0);
    load_stage(1, 1);
    load_stage(2, 2);

    for (int ch = 0; ch < nch; ch++) {
        if (ch < nch - 2)       { CP_WAIT(2); }
        else if (ch == nch - 2) { CP_WAIT(1); }
        else                    { CP_WAIT(0); }
        __syncthreads();   // single barrier per chunk (trailing one is redundant:
                           // 4-deep ring => load target (ch+3)%4 == (ch-1)%4 whose
                           // compute finished before every warp reached this barrier)
        if (ch + 3 < nch) load_stage(ch + 3, (ch + 3) & 3);

        const int buf = ch & 3;
        const uint32_t a_base = sm_b + (uint32_t)(buf * A_STG);
        const uint32_t b_base = sm_b + (uint32_t)(B_OFF + buf * B_STG);
#pragma unroll
        for (int kk = 0; kk < 2; kk++) {
            uint32_t af[4][4];
#pragma unroll
            for (int mt = 0; mt < 4; mt++) {
                uint32_t addr = a_base
                    + (uint32_t)((wm + mt * 16 + a_mloc) * 80)
                    + (uint32_t)(kk * 32 + a_koffB);
                ldsm_x4(af[mt], addr);
            }
            uint32_t bf[4][4];
#pragma unroll
            for (int nt16 = 0; nt16 < 4; nt16++) {
                uint32_t addr = b_base
                    + (uint32_t)((kk * 16 + b_kloc) * 272)
                    + (uint32_t)((wn + nt16 * 16 + b_nloc) * 2);
                ldsm_x4_t(bf[nt16], addr);
            }
#pragma unroll
            for (int mt = 0; mt < 4; mt++) {
#pragma unroll
                for (int nt16 = 0; nt16 < 4; nt16++) {
                    mma_f16(acc[mt][nt16 * 2 + 0], af[mt], &bf[nt16][0]);
                    mma_f16(acc[mt][nt16 * 2 + 1], af[mt], &bf[nt16][2]);
                }
            }
        }
    }

    // Epilogue: bias + store (64x64 per warp)
#pragma unroll
    for (int mt = 0; mt < 4; mt++) {
#pragma unroll
        for (int nt = 0; nt < 8; nt++) {
            int row = row0 + wm + mt * 16 + r;
            int col = col0 + wn + nt * 8 + c * 2;
            float2 bv = *(const float2*)(bias + col);
            float v00 = acc[mt][nt][0] + bv.x;
            float v01 = acc[mt][nt][1] + bv.y;
            float v10 = acc[mt][nt][2] + bv.x;
            float v11 = acc[mt][nt][3] + bv.y;
            if (OUT_HALF) {
                *(uint32_t*)&Ch[(size_t)row * N + col] = pack_f16(v01, v00);
                *(uint32_t*)&Ch[(size_t)(row + 8) * N + col] = pack_f16(v11, v10);
            } else {
                *(float2*)(Cf + (size_t)row * N + col) = make_float2(v00, v01);
                *(float2*)(Cf + (size_t)(row + 8) * N + col) = make_float2(v10, v11);
            }
        }
    }
}

// Proj GEMM: N=CH, K=CH, fp32 out
__global__ __launch_bounds__(128, 2)
void gemm_proj_kernel(const __half* __restrict__ A,
                      const __half* __restrict__ B,
                      const float* __restrict__ bias,
                      float* __restrict__ Cf) {
    extern __shared__ char smc[];
    gemm_body<false, CH, CH>(A, B, bias, Cf, nullptr,
                             blockIdx.y * 128, blockIdx.x * 128, smem_u32(smc));
}

// Fused qkv + prefix GEMM: grid y in [0,64) -> qkv problem, [64,68) -> prefix.
#define QKV_YB (BATCH * SEQ_T / 128)      // 64
__global__ __launch_bounds__(128, 2)
void gemm_qkvp_kernel(const __half* __restrict__ Ax,
                      const __half* __restrict__ Ap,
                      const __half* __restrict__ Bx,
                      const __half* __restrict__ Bp,
                      const float* __restrict__ biasx,
                      const float* __restrict__ biasp,
                      __half* __restrict__ Cx,
                      __half* __restrict__ Cp) {
    extern __shared__ char smc[];
    const int by = blockIdx.y;
    if (by < QKV_YB) {
        gemm_body<true, C3, CH>(Ax, Bx, biasx, nullptr, Cx,
                                by * 128, blockIdx.x * 128, smem_u32(smc));
    } else {
        gemm_body<true, C3, CH>(Ap, Bp, biasp, nullptr, Cp,
                                (by - QKV_YB) * 128, blockIdx.x * 128, smem_u32(smc));
    }
}

// ===========================================================================
// fp16 attention (R13 measured-best): 64-row Q tiles, 4 warps, cp.async
// double-buffered K/V, exp2 f16x2 softmax, ones-column MMA row sums, LPT.
// ===========================================================================
#define ATT_PAD 72
#define ATT_TILE_H (64 * ATT_PAD)
#define SCALE_LOG2E 0.18033688011112042f   // 0.125 * log2(e)

__global__ __launch_bounds__(128, 3)
void attn_f16_kernel(const __half* __restrict__ qkv,
                     const __half* __restrict__ pqkv,
                     __half* __restrict__ y) {
    __shared__ __half Qs[ATT_TILE_H];
    __shared__ __half Ks[2][ATT_TILE_H];
    __shared__ __half Vs[2][ATT_TILE_H];

    const int bh = blockIdx.x;
    const int b = bh / NHEAD;
    const int h = bh % NHEAD;
    const int qt = (gridDim.y - 1) - blockIdx.y;   // LPT: longest first
    const int tid = threadIdx.x;
    const int w = tid >> 5;
    const int lane = tid & 31;
    const int r = lane >> 2;
    const int c = lane & 3;

    const int mat = lane >> 3;
    const int m8r = lane & 7;
    const int mloc = (mat & 1) * 8 + m8r;
    const int koffB = (mat >> 1) * 16;

    const uint32_t qaddr = smem_u32(Qs);
    const uint32_t kaddr = smem_u32(Ks);
    const uint32_t vaddr = smem_u32(Vs);

    // Ones-column B fragment (constant): column 0 of B is all ones.
    const uint32_t bones_v = (r == 0) ? 0x3C003C00u : 0u;
    const uint32_t bones[2] = { bones_v, bones_v };

    // Load Q tile (64 rows x 64 halfs)
    const __half* qbase = qkv + (size_t)(b * SEQ_T + qt * 64) * C3 + h * HDIM;
#pragma unroll
    for (int i = 0; i < 4; i++) {
        int idx = tid + i * 128;
        int row = idx >> 3;
        int c8 = (idx & 7) * 8;
        *(uint4*)&Qs[row * ATT_PAD + c8] = *(const uint4*)(qbase + (size_t)row * C3 + c8);
    }
    __syncthreads();

    // Q fragments (constant across kv tiles)
    uint32_t aq[4][4];
#pragma unroll
    for (int ks = 0; ks < 4; ks++) {
        uint32_t addr = qaddr + (uint32_t)((w * 16 + mloc) * 144) + (uint32_t)(ks * 32 + koffB);
        ldsm_x4(aq[ks], addr);
    }

    float out[8][4];
#pragma unroll
    for (int nt = 0; nt < 8; nt++)
#pragma unroll
        for (int j = 0; j < 4; j++) out[nt][j] = 0.0f;

    const int lr0 = w * 16 + r;    // local q-row of row-group 0
    const int lr1 = lr0 + 8;

    // cp.async K/V tile loader
    auto load_kv = [&](const __half* kb, const __half* vb, int buf) {
#pragma unroll
        for (int i = 0; i < 2; i++) {
            int idx = tid + i * 128;
            int row = idx >> 3;
            int ck = idx & 7;
            cp16(kaddr + (uint32_t)(buf * ATT_TILE_H * 2 + row * 144 + ck * 16),
                 kb + (size_t)row * C3 + ck * 8);
        }
#pragma unroll
        for (int i = 2; i < 4; i++) {
            int idx = tid + (i - 2) * 128;
            int row = (idx >> 3) + 32;
            int ck = idx & 7;
            cp16(kaddr + (uint32_t)(buf * ATT_TILE_H * 2 + row * 144 + ck * 16),
                 kb + (size_t)row * C3 + ck * 8);
        }
#pragma unroll
        for (int i = 0; i < 2; i++) {
            int idx = tid + i * 128;
            int row = idx >> 3;
            int ck = idx & 7;
            cp16(vaddr + (uint32_t)(buf * ATT_TILE_H * 2 + row * 144 + ck * 16),
                 vb + (size_t)row * C3 + ck * 8);
        }
#pragma unroll
        for (int i = 2; i < 4; i++) {
            int idx = tid + (i - 2) * 128;
            int row = (idx >> 3) + 32;
            int ck = idx & 7;
            cp16(vaddr + (uint32_t)(buf * ATT_TILE_H * 2 + row * 144 + ck * 16),
                 vb + (size_t)row * C3 + ck * 8);
        }
        CP_COMMIT();
    };

    for (int pass = 0; pass < 2; pass++) {
        const int ntiles = (pass == 0) ? (qt + 1) : 1;
        const __half* src = (pass == 0) ? qkv : pqkv;
        const int rowbase = (pass == 0) ? (b * SEQ_T) : (b * SEQ_TP);
        const int mask_kt = (pass == 0) ? qt : (qt == 0 ? 0 : -1);

        float m0 = -1e30f, m1 = -1e30f;
        float ol[4] = {0.0f, 0.0f, 0.0f, 0.0f};   // l lives in col 0 (lane c==0)
        float o[8][4];
#pragma unroll
        for (int nt = 0; nt < 8; nt++)
#pragma unroll
            for (int j = 0; j < 4; j++) o[nt][j] = 0.0f;

        __syncthreads();
        {
            const __half* kb0 = src + (size_t)rowbase * C3 + CH + h * HDIM;
            load_kv(kb0, kb0 + CH, 0);
        }

        for (int kt = 0; kt < ntiles; kt++) {
            CP_WAIT(0);
            __syncthreads();
            if (kt + 1 < ntiles) {
                const __half* kbn = src + (size_t)(rowbase + (kt + 1) * 64) * C3 + CH + h * HDIM;
                load_kv(kbn, kbn + CH, (kt + 1) & 1);
            }
            const int buf = kt & 1;
            const uint32_t kbase = kaddr + (uint32_t)(buf * ATT_TILE_H * 2);
            const uint32_t vbase = vaddr + (uint32_t)(buf * ATT_TILE_H * 2);

            // S = Q K^T
            float s[8][4];
#pragma unroll
            for (int nt = 0; nt < 8; nt++)
#pragma unroll
                for (int j = 0; j < 4; j++) s[nt][j] = 0.0f;
#pragma unroll
            for (int ks = 0; ks < 4; ks++) {
#pragma unroll
                for (int nt16 = 0; nt16 < 4; nt16++) {
                    uint32_t bk[4];
                    uint32_t addr = kbase + (uint32_t)((nt16 * 16 + mloc) * 144)
                                  + (uint32_t)(ks * 32 + koffB);
                    ldsm_x4(bk, addr);
                    uint32_t b0[2] = { bk[0], bk[2] };
                    uint32_t b1[2] = { bk[1], bk[3] };
                    mma_f16(s[nt16 * 2 + 0], aq[ks], b0);
                    mma_f16(s[nt16 * 2 + 1], aq[ks], b1);
                }
            }

            // scale into exp2 domain; mask only on the diagonal tile
            if (kt == mask_kt) {
#pragma unroll
                for (int nt = 0; nt < 8; nt++) {
                    int lc = nt * 8 + 2 * c;
                    s[nt][0] = (lc     > lr0) ? -1e30f : s[nt][0] * SCALE_LOG2E;
                    s[nt][1] = (lc + 1 > lr0) ? -1e30f : s[nt][1] * SCALE_LOG2E;
                    s[nt][2] = (lc     > lr1) ? -1e30f : s[nt][2] * SCALE_LOG2E;
                    s[nt][3] = (lc + 1 > lr1) ? -1e30f : s[nt][3] * SCALE_LOG2E;
                }
            } else {
#pragma unroll
                for (int nt = 0; nt < 8; nt++) {
                    s[nt][0] *= SCALE_LOG2E;
                    s[nt][1] *= SCALE_LOG2E;
                    s[nt][2] *= SCALE_LOG2E;
                    s[nt][3] *= SCALE_LOG2E;
                }
            }

            // row max (exp2 domain)
            float mx0 = -1e30f, mx1 = -1e30f;
#pragma unroll
            for (int nt = 0; nt < 8; nt++) {
                mx0 = fmaxf(mx0, fmaxf(s[nt][0], s[nt][1]));
                mx1 = fmaxf(mx1, fmaxf(s[nt][2], s[nt][3]));
            }
            mx0 = fmaxf(mx0, __shfl_xor_sync(0xffffffffu, mx0, 1));
            mx0 = fmaxf(mx0, __shfl_xor_sync(0xffffffffu, mx0, 2));
            mx1 = fmaxf(mx1, __shfl_xor_sync(0xffffffffu, mx1, 1));
            mx1 = fmaxf(mx1, __shfl_xor_sync(0xffffffffu, mx1, 2));

            float mn0 = fmaxf(m0, mx0);
            float mn1 = fmaxf(m1, mx1);
            float a0 = ex2f(m0 - mn0);
            float a1 = ex2f(m1 - mn1);
            m0 = mn0; m1 = mn1;

            // P fragments via f16x2 ex2 (two values per MUFU op)
            uint32_t ph[8][2];
#pragma unroll
            for (int nt = 0; nt < 8; nt++) {
                ph[nt][0] = h2ex2(pack_f16(s[nt][1] - mn0, s[nt][0] - mn0));
                ph[nt][1] = h2ex2(pack_f16(s[nt][3] - mn1, s[nt][2] - mn1));
            }

            // rescale running O and l columns
#pragma unroll
            for (int nt = 0; nt < 8; nt++) {
                o[nt][0] *= a0; o[nt][1] *= a0;
                o[nt][2] *= a1; o[nt][3] *= a1;
            }
            ol[0] *= a0; ol[2] *= a1;

            // O += P V, and l += P @ ones (extra constant-fragment MMA)
#pragma unroll
            for (int kk = 0; kk < 4; kk++) {
                uint32_t ap[4];
                ap[0] = ph[2 * kk][0];
                ap[1] = ph[2 * kk][1];
                ap[2] = ph[2 * kk + 1][0];
                ap[3] = ph[2 * kk + 1][1];
                mma_f16(ol, ap, bones);
#pragma unroll
                for (int nt16 = 0; nt16 < 4; nt16++) {
                    uint32_t bv[4];
                    uint32_t addr = vbase + (uint32_t)((kk * 16 + mloc) * 144)
                                  + (uint32_t)(nt16 * 32 + koffB);
                    ldsm_x4_t(bv, addr);
                    mma_f16(o[nt16 * 2 + 0], ap, &bv[0]);
                    mma_f16(o[nt16 * 2 + 1], ap, &bv[2]);
                }
            }
        }

        // l broadcast from lane c==0 of each quad, then normalize & accumulate
        float l0 = __shfl_sync(0xffffffffu, ol[0], lane & 0x1C);
        float l1 = __shfl_sync(0xffffffffu, ol[2], lane & 0x1C);
        float inv0 = 1.0f / l0;
        float inv1 = 1.0f / l1;
#pragma unroll
        for (int nt = 0; nt < 8; nt++) {
            out[nt][0] += o[nt][0] * inv0;
            out[nt][1] += o[nt][1] * inv0;
            out[nt][2] += o[nt][2] * inv1;
            out[nt][3] += o[nt][3] * inv1;
        }
    }

    // Write y (fp16)
    {
        const int gr0 = qt * 64 + lr0;
        __half* y0 = y + (size_t)(b * SEQ_T + gr0) * CH + h * HDIM;
        __half* y1 = y0 + (size_t)8 * CH;
#pragma unroll
        for (int nt = 0; nt < 8; nt++) {
            int col = nt * 8 + 2 * c;
            *(uint32_t*)&y0[col] = pack_f16(out[nt][1], out[nt][0]);
            *(uint32_t*)&y1[col] = pack_f16(out[nt][3], out[nt][2]);
        }
    }
}

// ---------------------------------------------------------------------------
// Launch
// ---------------------------------------------------------------------------
extern "C" void kernel_launch(void* const* d_in, const int* in_sizes, int n_in,
                              void* d_out, int out_size) {
    const float* x        = (const float*)d_in[0];
    const float* prefix   = (const float*)d_in[1];
    const float* w_attn   = (const float*)d_in[2];
    const float* b_attn   = (const float*)d_in[3];
    const float* w_prefix = (const float*)d_in[4];
    const float* b_prefix = (const float*)d_in[5];
    const float* w_proj   = (const float*)d_in[6];
    const float* b_proj   = (const float*)d_in[7];
    float* out = (float*)d_out;

    __half *x16, *p16, *wa16, *wp16, *wo16, *qkv16, *pqkv16, *y16;
    cudaGetSymbolAddress((void**)&x16, g_x16);
    cudaGetSymbolAddress((void**)&p16, g_prefix16);
    cudaGetSymbolAddress((void**)&wa16, g_wattn16);
    cudaGetSymbolAddress((void**)&wp16, g_wprefix16);
    cudaGetSymbolAddress((void**)&wo16, g_wproj16);
    cudaGetSymbolAddress((void**)&qkv16, g_qkv16);
    cudaGetSymbolAddress((void**)&pqkv16, g_pqkv16);
    cudaGetSymbolAddress((void**)&y16, g_y16);

    cudaFuncSetAttribute(gemm_qkvp_kernel, cudaFuncAttributeMaxDynamicSharedMemorySize, GEMM_SMEM);
    cudaFuncSetAttribute(gemm_proj_kernel, cudaFuncAttributeMaxDynamicSharedMemorySize, GEMM_SMEM);

    // 0) fused fp32 -> fp16 conversion (single launch)
    cvt_all_f16<<<(CVT_TOT + 255) / 256, 256>>>(
        x, prefix, w_attn, w_prefix, w_proj,
        (uint32_t*)x16, (uint32_t*)p16, (uint32_t*)wa16, (uint32_t*)wp16, (uint32_t*)wo16);

    // 1) fused qkv + prefix GEMMs (fp16 out)
    {
        dim3 grid(C3 / 128, QKV_YB + (BATCH * SEQ_TP) / 128);   // (24, 68)
        gemm_qkvp_kernel<<<grid, 128, GEMM_SMEM>>>(x16, p16, wa16, wp16,
                                                   b_attn, b_prefix, qkv16, pqkv16);
    }
    // 2) attention -> y16 (fp16), LPT-ordered
    {
        dim3 grid(BATCH * NHEAD, SEQ_T / 64);
        attn_f16_kernel<<<grid, 128>>>(qkv16, pqkv16, y16);
    }
    // 3) out = y16 @ wproj16 + b_proj (fp32 out)
    {
        dim3 grid(CH / 128, (BATCH * SEQ_T) / 128);
        gemm_proj_kernel<<<grid, 128, GEMM_SMEM>>>(y16, wo16, b_proj, out);
    }
}

// round 16
// speedup vs baseline: 1.5152x; 1.5152x over previous
#include <cuda_runtime.h>
#include <cuda_fp16.h>
#include <math.h>
#include <stdint.h>

// Problem constants
#define BATCH 8
#define SEQ_T 1024
#define SEQ_TP 64
#define CH 1024
#define NHEAD 16
#define HDIM 64
#define C3 (3 * CH)

// Scratch (device globals: allocation-free rule)
__device__ __half g_x16[BATCH * SEQ_T * CH];
__device__ __half g_prefix16[BATCH * SEQ_TP * CH];
__device__ __half g_wattn16[CH * C3];
__device__ __half g_wprefix16[CH * C3];
__device__ __half g_wproj16[CH * CH];
__device__ __half g_qkv16[BATCH * SEQ_T * C3];
__device__ __half g_pqkv16[BATCH * SEQ_TP * C3];
__device__ __half g_y16[BATCH * SEQ_T * CH];

// ===========================================================================
// helpers (compute_80+ features only)
// ===========================================================================
__device__ __forceinline__ void mma_f16(float* d, const uint32_t* a, const uint32_t* b) {
    asm volatile(
        "mma.sync.aligned.m16n8k16.row.col.f32.f16.f16.f32 "
        "{%0,%1,%2,%3}, {%4,%5,%6,%7}, {%8,%9}, {%0,%1,%2,%3};"
        : "+f"(d[0]), "+f"(d[1]), "+f"(d[2]), "+f"(d[3])
        : "r"(a[0]), "r"(a[1]), "r"(a[2]), "r"(a[3]), "r"(b[0]), "r"(b[1]));
}

__device__ __forceinline__ void ldsm_x4(uint32_t* r, uint32_t addr) {
    asm volatile(
        "ldmatrix.sync.aligned.m8n8.x4.shared.b16 {%0,%1,%2,%3}, [%4];"
        : "=r"(r[0]), "=r"(r[1]), "=r"(r[2]), "=r"(r[3]) : "r"(addr));
}

__device__ __forceinline__ void ldsm_x4_t(uint32_t* r, uint32_t addr) {
    asm volatile(
        "ldmatrix.sync.aligned.m8n8.x4.trans.shared.b16 {%0,%1,%2,%3}, [%4];"
        : "=r"(r[0]), "=r"(r[1]), "=r"(r[2]), "=r"(r[3]) : "r"(addr));
}

// pack {hi, lo} -> f16x2 (lo in lower half)
__device__ __forceinline__ uint32_t pack_f16(float hi, float lo) {
    uint32_t h;
    asm("cvt.rn.f16x2.f32 %0, %1, %2;" : "=r"(h) : "f"(hi), "f"(lo));
    return h;
}

__device__ __forceinline__ float ex2f(float x) {
    float r;
    asm("ex2.approx.ftz.f32 %0, %1;" : "=f"(r) : "f"(x));
    return r;
}

// ex2 on packed f16x2 (one MUFU op for two values)
__device__ __forceinline__ uint32_t h2ex2(uint32_t x) {
    uint32_t r;
    asm("ex2.approx.f16x2 %0, %1;" : "=r"(r) : "r"(x));
    return r;
}

__device__ __forceinline__ uint32_t smem_u32(const void* p) {
    uint32_t a;
    asm("{ .reg .u64 t; cvta.to.shared.u64 t, %1; cvt.u32.u64 %0, t; }"
        : "=r"(a) : "l"(p));
    return a;
}

__device__ __forceinline__ void cp16(uint32_t dst, const void* src) {
    asm volatile("cp.async.cg.shared.global [%0], [%1], 16;" :: "r"(dst), "l"(src));
}
#define CP_COMMIT() asm volatile("cp.async.commit_group;" ::: "memory")
#define CP_WAIT(n)  asm volatile("cp.async.wait_group %0;" :: "n"(n) : "memory")

// ===========================================================================
// Fused fp32 -> fp16 conversion over all 5 tensors (one launch).
// ===========================================================================
#define CVT_N_X   (BATCH * SEQ_T * CH / 4)
#define CVT_N_P   (BATCH * SEQ_TP * CH / 4)
#define CVT_N_WA  (CH * C3 / 4)
#define CVT_N_WP  (CH * C3 / 4)
#define CVT_N_WO  (CH * CH / 4)
#define CVT_E1 (CVT_N_X)
#define CVT_E2 (CVT_E1 + CVT_N_P)
#define CVT_E3 (CVT_E2 + CVT_N_WA)
#define CVT_E4 (CVT_E3 + CVT_N_WP)
#define CVT_TOT (CVT_E4 + CVT_N_WO)

__global__ void cvt_all_f16(const float* __restrict__ x, const float* __restrict__ p,
                            const float* __restrict__ wa, const float* __restrict__ wp,
                            const float* __restrict__ wo,
                            uint32_t* __restrict__ ox, uint32_t* __restrict__ op,
                            uint32_t* __restrict__ owa, uint32_t* __restrict__ owp,
                            uint32_t* __restrict__ owo) {
    int i = blockIdx.x * blockDim.x + threadIdx.x;
    if (i >= CVT_TOT) return;
    const float* src;
    uint32_t* dst;
    int j;
    if (i < CVT_E1)      { src = x;  dst = ox;  j = i; }
    else if (i < CVT_E2) { src = p;  dst = op;  j = i - CVT_E1; }
    else if (i < CVT_E3) { src = wa; dst = owa; j = i - CVT_E2; }
    else if (i < CVT_E4) { src = wp; dst = owp; j = i - CVT_E3; }
    else                 { src = wo; dst = owo; j = i - CVT_E4; }
    float4 v = ((const float4*)src)[j];
    uint2 o;
    o.x = pack_f16(v.y, v.x);
    o.y = pack_f16(v.w, v.z);
    *(uint2*)&dst[2 * j] = o;
}

// ===========================================================================
// fp16 tensor-core GEMM body, compile-time dims: C = A[.,K] @ B[K,N] + bias.
// Block 128x128, BK=32, 128 thr (4 warps 2x2, warp tile 64x64).
// 4-stage cp.async ring, WAIT(2), BOTH barriers per chunk (R15 showed the
// trailing barrier is load-bearing for performance).
// ===========================================================================
#define A_STG 10240
#define B_STG 8704
#define NSTG 4
#define B_OFF (NSTG * A_STG)
#define GEMM_SMEM (B_OFF + NSTG * B_STG)   // 75776 bytes

template <bool OUT_HALF, int N, int K>
__device__ __forceinline__
void gemm_body(const __half* __restrict__ A,
               const __half* __restrict__ B,
               const float* __restrict__ bias,
               float* __restrict__ Cf,
               __half* __restrict__ Ch,
               int row0, int col0, uint32_t sm_b) {
    const int tid = threadIdx.x;
    const int wid = tid >> 5;
    const int lane = tid & 31;
    const int r = lane >> 2;
    const int c = lane & 3;
    const int wm = (wid >> 1) * 64;
    const int wn = (wid & 1) * 64;

    const int mat = lane >> 3;
    const int m8r = lane & 7;
    const int a_mloc = (mat & 1) * 8 + m8r;
    const int a_koffB = (mat >> 1) * 16;
    const int b_kloc = (mat & 1) * 8 + m8r;
    const int b_nloc = (mat >> 1) * 8;

    float acc[4][8][4];
#pragma unroll
    for (int mt = 0; mt < 4; mt++)
#pragma unroll
        for (int nt = 0; nt < 8; nt++)
#pragma unroll
            for (int j = 0; j < 4; j++) acc[mt][nt][j] = 0.0f;

    constexpr int nch = K >> 5;

    auto load_stage = [&](int ch, int st) {
#pragma unroll
        for (int i = 0; i < 4; i++) {
            int idx = tid + i * 128;
            int rw = idx >> 2;
            int ck = idx & 3;
            uint32_t dst = sm_b + (uint32_t)(st * A_STG + rw * 80 + ck * 16);
            cp16(dst, A + (size_t)(row0 + rw) * K + ch * 32 + ck * 8);
        }
#pragma unroll
        for (int i = 0; i < 4; i++) {
            int idx = tid + i * 128;
            int kk = idx >> 4;
            int ck = idx & 15;
            uint32_t dst = sm_b + (uint32_t)(B_OFF + st * B_STG + kk * 272 + ck * 16);
            cp16(dst, B + (size_t)(ch * 32 + kk) * N + col0 + ck * 8);
        }
        CP_COMMIT();
    };

    load_stage(0, 0);
    load_stage(1, 1);
    load_stage(2, 2);

    for (int ch = 0; ch < nch; ch++) {
        if (ch < nch - 2)       { CP_WAIT(2); }
        else if (ch == nch - 2) { CP_WAIT(1); }
        else                    { CP_WAIT(0); }
        __syncthreads();
        if (ch + 3 < nch) load_stage(ch + 3, (ch + 3) & 3);

        const int buf = ch & 3;
        const uint32_t a_base = sm_b + (uint32_t)(buf * A_STG);
        const uint32_t b_base = sm_b + (uint32_t)(B_OFF + buf * B_STG);
#pragma unroll
        for (int kk = 0; kk < 2; kk++) {
            uint32_t af[4][4];
#pragma unroll
            for (int mt = 0; mt < 4; mt++) {
                uint32_t addr = a_base
                    + (uint32_t)((wm + mt * 16 + a_mloc) * 80)
                    + (uint32_t)(kk * 32 + a_koffB);
                ldsm_x4(af[mt], addr);
            }
            uint32_t bf[4][4];
#pragma unroll
            for (int nt16 = 0; nt16 < 4; nt16++) {
                uint32_t addr = b_base
                    + (uint32_t)((kk * 16 + b_kloc) * 272)
                    + (uint32_t)((wn + nt16 * 16 + b_nloc) * 2);
                ldsm_x4_t(bf[nt16], addr);
            }
#pragma unroll
            for (int mt = 0; mt < 4; mt++) {
#pragma unroll
                for (int nt16 = 0; nt16 < 4; nt16++) {
                    mma_f16(acc[mt][nt16 * 2 + 0], af[mt], &bf[nt16][0]);
                    mma_f16(acc[mt][nt16 * 2 + 1], af[mt], &bf[nt16][2]);
                }
            }
        }
        __syncthreads();
    }

    // Epilogue: bias + store (64x64 per warp)
#pragma unroll
    for (int mt = 0; mt < 4; mt++) {
#pragma unroll
        for (int nt = 0; nt < 8; nt++) {
            int row = row0 + wm + mt * 16 + r;
            int col = col0 + wn + nt * 8 + c * 2;
            float2 bv = *(const float2*)(bias + col);
            float v00 = acc[mt][nt][0] + bv.x;
            float v01 = acc[mt][nt][1] + bv.y;
            float v10 = acc[mt][nt][2] + bv.x;
            float v11 = acc[mt][nt][3] + bv.y;
            if (OUT_HALF) {
                *(uint32_t*)&Ch[(size_t)row * N + col] = pack_f16(v01, v00);
                *(uint32_t*)&Ch[(size_t)(row + 8) * N + col] = pack_f16(v11, v10);
            } else {
                *(float2*)(Cf + (size_t)row * N + col) = make_float2(v00, v01);
                *(float2*)(Cf + (size_t)(row + 8) * N + col) = make_float2(v10, v11);
            }
        }
    }
}

// Proj GEMM: N=CH, K=CH, fp32 out
__global__ __launch_bounds__(128, 2)
void gemm_proj_kernel(const __half* __restrict__ A,
                      const __half* __restrict__ B,
                      const float* __restrict__ bias,
                      float* __restrict__ Cf) {
    extern __shared__ char smc[];
    gemm_body<false, CH, CH>(A, B, bias, Cf, nullptr,
                             blockIdx.y * 128, blockIdx.x * 128, smem_u32(smc));
}

// Fused qkv + prefix GEMM: grid y in [0,64) -> qkv problem, [64,68) -> prefix.
#define QKV_YB (BATCH * SEQ_T / 128)      // 64
__global__ __launch_bounds__(128, 2)
void gemm_qkvp_kernel(const __half* __restrict__ Ax,
                      const __half* __restrict__ Ap,
                      const __half* __restrict__ Bx,
                      const __half* __restrict__ Bp,
                      const float* __restrict__ biasx,
                      const float* __restrict__ biasp,
                      __half* __restrict__ Cx,
                      __half* __restrict__ Cp) {
    extern __shared__ char smc[];
    const int by = blockIdx.y;
    if (by < QKV_YB) {
        gemm_body<true, C3, CH>(Ax, Bx, biasx, nullptr, Cx,
                                by * 128, blockIdx.x * 128, smem_u32(smc));
    } else {
        gemm_body<true, C3, CH>(Ap, Bp, biasp, nullptr, Cp,
                                (by - QKV_YB) * 128, blockIdx.x * 128, smem_u32(smc));
    }
}

// ===========================================================================
// fp16 attention (R13 measured-best): 64-row Q tiles, 4 warps, cp.async
// double-buffered K/V, exp2 f16x2 softmax, ones-column MMA row sums, LPT.
// ===========================================================================
#define ATT_PAD 72
#define ATT_TILE_H (64 * ATT_PAD)
#define SCALE_LOG2E 0.18033688011112042f   // 0.125 * log2(e)

__global__ __launch_bounds__(128, 3)
void attn_f16_kernel(const __half* __restrict__ qkv,
                     const __half* __restrict__ pqkv,
                     __half* __restrict__ y) {
    __shared__ __half Qs[ATT_TILE_H];
    __shared__ __half Ks[2][ATT_TILE_H];
    __shared__ __half Vs[2][ATT_TILE_H];

    const int bh = blockIdx.x;
    const int b = bh / NHEAD;
    const int h = bh % NHEAD;
    const int qt = (gridDim.y - 1) - blockIdx.y;   // LPT: longest first
    const int tid = threadIdx.x;
    const int w = tid >> 5;
    const int lane = tid & 31;
    const int r = lane >> 2;
    const int c = lane & 3;

    const int mat = lane >> 3;
    const int m8r = lane & 7;
    const int mloc = (mat & 1) * 8 + m8r;
    const int koffB = (mat >> 1) * 16;

    const uint32_t qaddr = smem_u32(Qs);
    const uint32_t kaddr = smem_u32(Ks);
    const uint32_t vaddr = smem_u32(Vs);

    // Ones-column B fragment (constant): column 0 of B is all ones.
    const uint32_t bones_v = (r == 0) ? 0x3C003C00u : 0u;
    const uint32_t bones[2] = { bones_v, bones_v };

    // Load Q tile (64 rows x 64 halfs)
    const __half* qbase = qkv + (size_t)(b * SEQ_T + qt * 64) * C3 + h * HDIM;
#pragma unroll
    for (int i = 0; i < 4; i++) {
        int idx = tid + i * 128;
        int row = idx >> 3;
        int c8 = (idx & 7) * 8;
        *(uint4*)&Qs[row * ATT_PAD + c8] = *(const uint4*)(qbase + (size_t)row * C3 + c8);
    }
    __syncthreads();

    // Q fragments (constant across kv tiles)
    uint32_t aq[4][4];
#pragma unroll
    for (int ks = 0; ks < 4; ks++) {
        uint32_t addr = qaddr + (uint32_t)((w * 16 + mloc) * 144) + (uint32_t)(ks * 32 + koffB);
        ldsm_x4(aq[ks], addr);
    }

    float out[8][4];
#pragma unroll
    for (int nt = 0; nt < 8; nt++)
#pragma unroll
        for (int j = 0; j < 4; j++) out[nt][j] = 0.0f;

    const int lr0 = w * 16 + r;    // local q-row of row-group 0
    const int lr1 = lr0 + 8;

    // cp.async K/V tile loader
    auto load_kv = [&](const __half* kb, const __half* vb, int buf) {
#pragma unroll
        for (int i = 0; i < 2; i++) {
            int idx = tid + i * 128;
            int row = idx >> 3;
            int ck = idx & 7;
            cp16(kaddr + (uint32_t)(buf * ATT_TILE_H * 2 + row * 144 + ck * 16),
                 kb + (size_t)row * C3 + ck * 8);
        }
#pragma unroll
        for (int i = 2; i < 4; i++) {
            int idx = tid + (i - 2) * 128;
            int row = (idx >> 3) + 32;
            int ck = idx & 7;
            cp16(kaddr + (uint32_t)(buf * ATT_TILE_H * 2 + row * 144 + ck * 16),
                 kb + (size_t)row * C3 + ck * 8);
        }
#pragma unroll
        for (int i = 0; i < 2; i++) {
            int idx = tid + i * 128;
            int row = idx >> 3;
            int ck = idx & 7;
            cp16(vaddr + (uint32_t)(buf * ATT_TILE_H * 2 + row * 144 + ck * 16),
                 vb + (size_t)row * C3 + ck * 8);
        }
#pragma unroll
        for (int i = 2; i < 4; i++) {
            int idx = tid + (i - 2) * 128;
            int row = (idx >> 3) + 32;
            int ck = idx & 7;
            cp16(vaddr + (uint32_t)(buf * ATT_TILE_H * 2 + row * 144 + ck * 16),
                 vb + (size_t)row * C3 + ck * 8);
        }
        CP_COMMIT();
    };

    for (int pass = 0; pass < 2; pass++) {
        const int ntiles = (pass == 0) ? (qt + 1) : 1;
        const __half* src = (pass == 0) ? qkv : pqkv;
        const int rowbase = (pass == 0) ? (b * SEQ_T) : (b * SEQ_TP);
        const int mask_kt = (pass == 0) ? qt : (qt == 0 ? 0 : -1);

        float m0 = -1e30f, m1 = -1e30f;
        float ol[4] = {0.0f, 0.0f, 0.0f, 0.0f};   // l lives in col 0 (lane c==0)
        float o[8][4];
#pragma unroll
        for (int nt = 0; nt < 8; nt++)
#pragma unroll
            for (int j = 0; j < 4; j++) o[nt][j] = 0.0f;

        __syncthreads();
        {
            const __half* kb0 = src + (size_t)rowbase * C3 + CH + h * HDIM;
            load_kv(kb0, kb0 + CH, 0);
        }

        for (int kt = 0; kt < ntiles; kt++) {
            CP_WAIT(0);
            __syncthreads();
            if (kt + 1 < ntiles) {
                const __half* kbn = src + (size_t)(rowbase + (kt + 1) * 64) * C3 + CH + h * HDIM;
                load_kv(kbn, kbn + CH, (kt + 1) & 1);
            }
            const int buf = kt & 1;
            const uint32_t kbase = kaddr + (uint32_t)(buf * ATT_TILE_H * 2);
            const uint32_t vbase = vaddr + (uint32_t)(buf * ATT_TILE_H * 2);

            // S = Q K^T
            float s[8][4];
#pragma unroll
            for (int nt = 0; nt < 8; nt++)
#pragma unroll
                for (int j = 0; j < 4; j++) s[nt][j] = 0.0f;
#pragma unroll
            for (int ks = 0; ks < 4; ks++) {
#pragma unroll
                for (int nt16 = 0; nt16 < 4; nt16++) {
                    uint32_t bk[4];
                    uint32_t addr = kbase + (uint32_t)((nt16 * 16 + mloc) * 144)
                                  + (uint32_t)(ks * 32 + koffB);
                    ldsm_x4(bk, addr);
                    uint32_t b0[2] = { bk[0], bk[2] };
                    uint32_t b1[2] = { bk[1], bk[3] };
                    mma_f16(s[nt16 * 2 + 0], aq[ks], b0);
                    mma_f16(s[nt16 * 2 + 1], aq[ks], b1);
                }
            }

            // scale into exp2 domain; mask only on the diagonal tile
            if (kt == mask_kt) {
#pragma unroll
                for (int nt = 0; nt < 8; nt++) {
                    int lc = nt * 8 + 2 * c;
                    s[nt][0] = (lc     > lr0) ? -1e30f : s[nt][0] * SCALE_LOG2E;
                    s[nt][1] = (lc + 1 > lr0) ? -1e30f : s[nt][1] * SCALE_LOG2E;
                    s[nt][2] = (lc     > lr1) ? -1e30f : s[nt][2] * SCALE_LOG2E;
                    s[nt][3] = (lc + 1 > lr1) ? -1e30f : s[nt][3] * SCALE_LOG2E;
                }
            } else {
#pragma unroll
                for (int nt = 0; nt < 8; nt++) {
                    s[nt][0] *= SCALE_LOG2E;
                    s[nt][1] *= SCALE_LOG2E;
                    s[nt][2] *= SCALE_LOG2E;
                    s[nt][3] *= SCALE_LOG2E;
                }
            }

            // row max (exp2 domain)
            float mx0 = -1e30f, mx1 = -1e30f;
#pragma unroll
            for (int nt = 0; nt < 8; nt++) {
                mx0 = fmaxf(mx0, fmaxf(s[nt][0], s[nt][1]));
                mx1 = fmaxf(mx1, fmaxf(s[nt][2], s[nt][3]));
            }
            mx0 = fmaxf(mx0, __shfl_xor_sync(0xffffffffu, mx0, 1));
            mx0 = fmaxf(mx0, __shfl_xor_sync(0xffffffffu, mx0, 2));
            mx1 = fmaxf(mx1, __shfl_xor_sync(0xffffffffu, mx1, 1));
            mx1 = fmaxf(mx1, __shfl_xor_sync(0xffffffffu, mx1, 2));

            float mn0 = fmaxf(m0, mx0);
            float mn1 = fmaxf(m1, mx1);
            float a0 = ex2f(m0 - mn0);
            float a1 = ex2f(m1 - mn1);
            m0 = mn0; m1 = mn1;

            // P fragments via f16x2 ex2 (two values per MUFU op)
            uint32_t ph[8][2];
#pragma unroll
            for (int nt = 0; nt < 8; nt++) {
                ph[nt][0] = h2ex2(pack_f16(s[nt][1] - mn0, s[nt][0] - mn0));
                ph[nt][1] = h2ex2(pack_f16(s[nt][3] - mn1, s[nt][2] - mn1));
            }

            // rescale running O and l columns
#pragma unroll
            for (int nt = 0; nt < 8; nt++) {
                o[nt][0] *= a0; o[nt][1] *= a0;
                o[nt][2] *= a1; o[nt][3] *= a1;
            }
            ol[0] *= a0; ol[2] *= a1;

            // O += P V, and l += P @ ones (extra constant-fragment MMA)
#pragma unroll
            for (int kk = 0; kk < 4; kk++) {
                uint32_t ap[4];
                ap[0] = ph[2 * kk][0];
                ap[1] = ph[2 * kk][1];
                ap[2] = ph[2 * kk + 1][0];
                ap[3] = ph[2 * kk + 1][1];
                mma_f16(ol, ap, bones);
#pragma unroll
                for (int nt16 = 0; nt16 < 4; nt16++) {
                    uint32_t bv[4];
                    uint32_t addr = vbase + (uint32_t)((kk * 16 + mloc) * 144)
                                  + (uint32_t)(nt16 * 32 + koffB);
                    ldsm_x4_t(bv, addr);
                    mma_f16(o[nt16 * 2 + 0], ap, &bv[0]);
                    mma_f16(o[nt16 * 2 + 1], ap, &bv[2]);
                }
            }
        }

        // l broadcast from lane c==0 of each quad, then normalize & accumulate
        float l0 = __shfl_sync(0xffffffffu, ol[0], lane & 0x1C);
        float l1 = __shfl_sync(0xffffffffu, ol[2], lane & 0x1C);
        float inv0 = 1.0f / l0;
        float inv1 = 1.0f / l1;
#pragma unroll
        for (int nt = 0; nt < 8; nt++) {
            out[nt][0] += o[nt][0] * inv0;
            out[nt][1] += o[nt][1] * inv0;
            out[nt][2] += o[nt][2] * inv1;
            out[nt][3] += o[nt][3] * inv1;
        }
    }

    // Write y (fp16)
    {
        const int gr0 = qt * 64 + lr0;
        __half* y0 = y + (size_t)(b * SEQ_T + gr0) * CH + h * HDIM;
        __half* y1 = y0 + (size_t)8 * CH;
#pragma unroll
        for (int nt = 0; nt < 8; nt++) {
            int col = nt * 8 + 2 * c;
            *(uint32_t*)&y0[col] = pack_f16(out[nt][1], out[nt][0]);
            *(uint32_t*)&y1[col] = pack_f16(out[nt][3], out[nt][2]);
        }
    }
}

// ---------------------------------------------------------------------------
// Launch
// ---------------------------------------------------------------------------
extern "C" void kernel_launch(void* const* d_in, const int* in_sizes, int n_in,
                              void* d_out, int out_size) {
    const float* x        = (const float*)d_in[0];
    const float* prefix   = (const float*)d_in[1];
    const float* w_attn   = (const float*)d_in[2];
    const float* b_attn   = (const float*)d_in[3];
    const float* w_prefix = (const float*)d_in[4];
    const float* b_prefix = (const float*)d_in[5];
    const float* w_proj   = (const float*)d_in[6];
    const float* b_proj   = (const float*)d_in[7];
    float* out = (float*)d_out;

    __half *x16, *p16, *wa16, *wp16, *wo16, *qkv16, *pqkv16, *y16;
    cudaGetSymbolAddress((void**)&x16, g_x16);
    cudaGetSymbolAddress((void**)&p16, g_prefix16);
    cudaGetSymbolAddress((void**)&wa16, g_wattn16);
    cudaGetSymbolAddress((void**)&wp16, g_wprefix16);
    cudaGetSymbolAddress((void**)&wo16, g_wproj16);
    cudaGetSymbolAddress((void**)&qkv16, g_qkv16);
    cudaGetSymbolAddress((void**)&pqkv16, g_pqkv16);
    cudaGetSymbolAddress((void**)&y16, g_y16);

    cudaFuncSetAttribute(gemm_qkvp_kernel, cudaFuncAttributeMaxDynamicSharedMemorySize, GEMM_SMEM);
    cudaFuncSetAttribute(gemm_proj_kernel, cudaFuncAttributeMaxDynamicSharedMemorySize, GEMM_SMEM);

    // 0) fused fp32 -> fp16 conversion (single launch)
    cvt_all_f16<<<(CVT_TOT + 255) / 256, 256>>>(
        x, prefix, w_attn, w_prefix, w_proj,
        (uint32_t*)x16, (uint32_t*)p16, (uint32_t*)wa16, (uint32_t*)wp16, (uint32_t*)wo16);

    // 1) fused qkv + prefix GEMMs (fp16 out)
    {
        dim3 grid(C3 / 128, QKV_YB + (BATCH * SEQ_TP) / 128);   // (24, 68)
        gemm_qkvp_kernel<<<grid, 128, GEMM_SMEM>>>(x16, p16, wa16, wp16,
                                                   b_attn, b_prefix, qkv16, pqkv16);
    }
    // 2) attention -> y16 (fp16), LPT-ordered
    {
        dim3 grid(BATCH * NHEAD, SEQ_T / 64);
        attn_f16_kernel<<<grid, 128>>>(qkv16, pqkv16, y16);
    }
    // 3) out = y16 @ wproj16 + b_proj (fp32 out)
    {
        dim3 grid(CH / 128, (BATCH * SEQ_T) / 128);
        gemm_proj_kernel<<<grid, 128, GEMM_SMEM>>>(y16, wo16, b_proj, out);
    }
}